// round 4
// baseline (speedup 1.0000x reference)
#include <cuda_runtime.h>
#include <cstdint>

#define NPTS 1000000
#define C 128
#define G 100000

// Scratch: group sums [G, C] and counts [G] (device globals — no allocation).
__device__ float g_sums[(size_t)G * C];
__device__ float g_counts[G];

// ---------------------------------------------------------------------------
// Kernel 1: zero the accumulators (float4 stores).
// ---------------------------------------------------------------------------
__global__ void zero_kernel() {
    const int stride = gridDim.x * blockDim.x;
    int idx = blockIdx.x * blockDim.x + threadIdx.x;
    const int total4 = (G * C) / 4;  // 3.2M float4
    float4 z = make_float4(0.f, 0.f, 0.f, 0.f);
    float4* s4 = reinterpret_cast<float4*>(g_sums);
    for (int i = idx; i < total4; i += stride) s4[i] = z;
    for (int i = idx; i < G; i += stride) g_counts[i] = 0.f;
}

// ---------------------------------------------------------------------------
// Kernel 2: scatter-add. One warp per point. Each lane handles one float4
// (4 channels); vector atomicAdd (float4) -> RED.E.ADD.v4 into L2.
// group_ids is int32 (JAX default config downgrades int64 -> int32).
// ---------------------------------------------------------------------------
__global__ void __launch_bounds__(256) scatter_kernel(
    const float* __restrict__ feat,
    const int* __restrict__ gid,
    int n)
{
    int warp = (blockIdx.x * blockDim.x + threadIdx.x) >> 5;
    int lane = threadIdx.x & 31;
    if (warp >= n) return;

    int g = gid[warp];                 // same addr for all lanes -> broadcast
    g = min(max(g, 0), G - 1);         // safety clamp (diagnostic, ~free)

    const float4* frow = reinterpret_cast<const float4*>(feat + (size_t)warp * C);
    float4 v = frow[lane];

    float4* srow = reinterpret_cast<float4*>(g_sums + (size_t)g * C);
    atomicAdd(srow + lane, v);         // sm_90+: red.global.add.v4.f32

    if (lane == 0) atomicAdd(&g_counts[g], 1.0f);
}

// ---------------------------------------------------------------------------
// Kernel 3: fused normalize + gather. One warp per point.
// out[p] = sums[gid[p]] / max(counts[gid[p]], 1)
// sums (51 MB) stays L2-resident, so reads mostly hit L2.
// ---------------------------------------------------------------------------
__global__ void __launch_bounds__(256) gather_kernel(
    const int* __restrict__ gid,
    float* __restrict__ out,
    int n)
{
    int warp = (blockIdx.x * blockDim.x + threadIdx.x) >> 5;
    int lane = threadIdx.x & 31;
    if (warp >= n) return;

    int g = gid[warp];
    g = min(max(g, 0), G - 1);

    float inv = 1.0f / fmaxf(g_counts[g], 1.0f);

    const float4* srow = reinterpret_cast<const float4*>(g_sums + (size_t)g * C);
    float4 v = srow[lane];
    v.x *= inv; v.y *= inv; v.z *= inv; v.w *= inv;

    float4* orow = reinterpret_cast<float4*>(out + (size_t)warp * C);
    orow[lane] = v;
}

// ---------------------------------------------------------------------------
// Launch. Inputs (metadata order): [0] ref_bxyz (unused), [1] ref_feat f32,
// [2] group_ids int32. Output: [N, C] f32.
// ---------------------------------------------------------------------------
extern "C" void kernel_launch(void* const* d_in, const int* in_sizes, int n_in,
                              void* d_out, int out_size) {
    const float* feat = (const float*)d_in[1];
    const int* gid = (const int*)d_in[2];
    float* out = (float*)d_out;

    const int n = in_sizes[2];  // number of points (1M)

    // 1) zero accumulators
    zero_kernel<<<1184, 256>>>();

    // 2) scatter-add: 1 warp per point, 8 warps per block
    int blocks = (n + 7) / 8;
    scatter_kernel<<<blocks, 256>>>(feat, gid, n);

    // 3) fused divide + gather
    gather_kernel<<<blocks, 256>>>(gid, out, n);
}

// round 5
// speedup vs baseline: 1.6834x; 1.6834x over previous
#include <cuda_runtime.h>
#include <cstdint>

#define C 128
#define G 100000
#define NPTS_MAX 1000000

// Scratch (device globals — no allocation).
__device__ int g_hist[G];        // per-group counts
__device__ int g_ofs[G];         // per-group start offset into perm
__device__ int g_cur[G];         // running cursor (consumed by perm_kernel)
__device__ int g_perm[NPTS_MAX]; // point indices, grouped contiguously
__device__ int g_block_base;     // global offset counter

// ---------------------------------------------------------------------------
// 1) zero histogram + global counter
// ---------------------------------------------------------------------------
__global__ void init_kernel() {
    int idx = blockIdx.x * blockDim.x + threadIdx.x;
    int stride = gridDim.x * blockDim.x;
    for (int i = idx; i < G; i += stride) g_hist[i] = 0;
    if (idx == 0) g_block_base = 0;
}

// ---------------------------------------------------------------------------
// 2) histogram of group ids
// ---------------------------------------------------------------------------
__global__ void __launch_bounds__(256) hist_kernel(
    const int* __restrict__ gid, int n)
{
    int p = blockIdx.x * blockDim.x + threadIdx.x;
    if (p >= n) return;
    int g = gid[p];
    g = min(max(g, 0), G - 1);
    atomicAdd(&g_hist[g], 1);
}

// ---------------------------------------------------------------------------
// 3) offsets: block-local exclusive scan + one atomicAdd per block for the
//    global base. Group ordering in memory is nondeterministic across blocks;
//    irrelevant — each group just needs a contiguous region.
// ---------------------------------------------------------------------------
__global__ void __launch_bounds__(256) offsets_kernel()
{
    __shared__ int s[256];
    __shared__ int base;
    int t = threadIdx.x;
    int g = blockIdx.x * 256 + t;
    int cnt = (g < G) ? g_hist[g] : 0;
    s[t] = cnt;
    __syncthreads();
    // Hillis-Steele inclusive scan
    for (int d = 1; d < 256; d <<= 1) {
        int v = 0;
        if (t >= d) v = s[t - d];
        __syncthreads();
        if (t >= d) s[t] += v;
        __syncthreads();
    }
    int excl = s[t] - cnt;
    if (t == 255) base = atomicAdd(&g_block_base, s[255]);
    __syncthreads();
    if (g < G) {
        int o = base + excl;
        g_ofs[g] = o;
        g_cur[g] = o;
    }
}

// ---------------------------------------------------------------------------
// 4) build permutation: each point claims a slot in its group's region
// ---------------------------------------------------------------------------
__global__ void __launch_bounds__(256) perm_kernel(
    const int* __restrict__ gid, int n)
{
    int p = blockIdx.x * blockDim.x + threadIdx.x;
    if (p >= n) return;
    int g = gid[p];
    g = min(max(g, 0), G - 1);
    int pos = atomicAdd(&g_cur[g], 1);
    g_perm[pos] = p;
}

// ---------------------------------------------------------------------------
// 5) group-major reduce + broadcast write. One warp per group: 32 lanes hold
//    the full 128-channel accumulator as float4 in registers. Zero float
//    atomics. Mean written directly to every member point's output row.
// ---------------------------------------------------------------------------
__global__ void __launch_bounds__(256) reduce_write_kernel(
    const float* __restrict__ feat,
    float* __restrict__ out)
{
    int warp = (blockIdx.x * blockDim.x + threadIdx.x) >> 5;
    int lane = threadIdx.x & 31;
    if (warp >= G) return;

    int start = g_ofs[warp];
    int cnt   = g_hist[warp];
    if (cnt == 0) return;

    float4 acc = make_float4(0.f, 0.f, 0.f, 0.f);

    // software-pipelined: prefetch next perm entry while loading current row
    int p = g_perm[start];
    for (int i = 0; i < cnt; i++) {
        int pn = (i + 1 < cnt) ? g_perm[start + i + 1] : 0;
        const float4* frow = reinterpret_cast<const float4*>(feat + (size_t)p * C);
        float4 v = frow[lane];
        acc.x += v.x; acc.y += v.y; acc.z += v.z; acc.w += v.w;
        p = pn;
    }

    float inv = 1.0f / (float)cnt;
    acc.x *= inv; acc.y *= inv; acc.z *= inv; acc.w *= inv;

    for (int i = 0; i < cnt; i++) {
        int q = g_perm[start + i];  // L1/L2 hit (just read in loop above)
        float4* orow = reinterpret_cast<float4*>(out + (size_t)q * C);
        orow[lane] = acc;
    }
}

// ---------------------------------------------------------------------------
// Launch. Inputs: [0] ref_bxyz (unused), [1] ref_feat f32 [N,128],
// [2] group_ids int32 [N]. Output: [N,128] f32.
// ---------------------------------------------------------------------------
extern "C" void kernel_launch(void* const* d_in, const int* in_sizes, int n_in,
                              void* d_out, int out_size) {
    const float* feat = (const float*)d_in[1];
    const int* gid = (const int*)d_in[2];
    float* out = (float*)d_out;

    const int n = in_sizes[2];  // 1M points

    init_kernel<<<592, 256>>>();

    int pblocks = (n + 255) / 256;
    hist_kernel<<<pblocks, 256>>>(gid, n);

    offsets_kernel<<<(G + 255) / 256, 256>>>();

    perm_kernel<<<pblocks, 256>>>(gid, n);

    // one warp per group, 8 warps per block
    reduce_write_kernel<<<(G + 7) / 8, 256>>>(feat, out);
}